// round 9
// baseline (speedup 1.0000x reference)
#include <cuda_runtime.h>
#include <cuda_bf16.h>
#include <cstdint>

// dist[i,j] = ||s_i||^2 + ||t_j||^2 - 2 <s_i, t_j>
// s: [n, 64] fp32, t: [q, 64] fp32, out: [n, q] fp32. n = q = 16384.
// bf16 mma.m16n8k16 + ldmatrix; cp.async.bulk staging of pre-swizzled tiles;
// 64x64 warp tiles (4 warps, 128x128 CTA) to minimize ldmatrix traffic;
// quad-butterfly epilogue with STG.128.

#define D    64
#define BM   128
#define BN   128
#define MAXNQ 16384

__device__ float g_s_sq[MAXNQ];
__device__ float g_t_sq[MAXNQ];
// Pre-swizzled bf16 tiles: within each 128B row, 16B chunk c stored at c^(row&7).
__device__ __nv_bfloat16 g_s_bf[MAXNQ * D];
__device__ __nv_bfloat16 g_t_bf[MAXNQ * D];

// ---------------- prep: fp32 -> pre-swizzled bf16 + row norms ----------------
__global__ void prep_kernel(const float* __restrict__ s,
                            const float* __restrict__ t, int n, int q) {
    const float* src = blockIdx.y ? t : s;
    __nv_bfloat16* dstb = blockIdx.y ? g_t_bf : g_s_bf;
    float* dstn = blockIdx.y ? g_t_sq : g_s_sq;
    const int lim = blockIdx.y ? q : n;
    const int row = blockIdx.x * 64 + (threadIdx.x >> 2);
    const int part = threadIdx.x & 3;
    if (row >= lim) return;
    const float4* p = reinterpret_cast<const float4*>(src + (size_t)row * D) + part * 4;
    float acc = 0.f;
    uint4* rowq = reinterpret_cast<uint4*>(dstb + (size_t)row * D);
    const int sw = row & 7;
#pragma unroll
    for (int j = 0; j < 2; j++) {
        float4 a = p[2 * j], b = p[2 * j + 1];
        acc += a.x * a.x + a.y * a.y + a.z * a.z + a.w * a.w;
        acc += b.x * b.x + b.y * b.y + b.z * b.z + b.w * b.w;
        __nv_bfloat162 h0 = __float22bfloat162_rn(make_float2(a.x, a.y));
        __nv_bfloat162 h1 = __float22bfloat162_rn(make_float2(a.z, a.w));
        __nv_bfloat162 h2 = __float22bfloat162_rn(make_float2(b.x, b.y));
        __nv_bfloat162 h3 = __float22bfloat162_rn(make_float2(b.z, b.w));
        uint4 u;
        u.x = *reinterpret_cast<uint32_t*>(&h0);
        u.y = *reinterpret_cast<uint32_t*>(&h1);
        u.z = *reinterpret_cast<uint32_t*>(&h2);
        u.w = *reinterpret_cast<uint32_t*>(&h3);
        rowq[(part * 2 + j) ^ sw] = u;   // pre-apply ldmatrix swizzle
    }
    acc += __shfl_xor_sync(0xFFFFFFFF, acc, 1);
    acc += __shfl_xor_sync(0xFFFFFFFF, acc, 2);
    if (part == 0) dstn[row] = acc;
}

// ---------------- helpers ----------------
__device__ __forceinline__ void ldsm_x4(uint32_t& r0, uint32_t& r1,
                                        uint32_t& r2, uint32_t& r3,
                                        uint32_t addr) {
    asm volatile("ldmatrix.sync.aligned.m8n8.x4.shared.b16 {%0,%1,%2,%3}, [%4];"
                 : "=r"(r0), "=r"(r1), "=r"(r2), "=r"(r3) : "r"(addr));
}

__device__ __forceinline__ void mma_bf16(float c[4], const uint32_t a[4],
                                         uint32_t b0, uint32_t b1) {
    asm volatile(
        "mma.sync.aligned.m16n8k16.row.col.f32.bf16.bf16.f32 "
        "{%0,%1,%2,%3}, {%4,%5,%6,%7}, {%8,%9}, {%0,%1,%2,%3};"
        : "+f"(c[0]), "+f"(c[1]), "+f"(c[2]), "+f"(c[3])
        : "r"(a[0]), "r"(a[1]), "r"(a[2]), "r"(a[3]), "r"(b0), "r"(b1));
}

__device__ __forceinline__ float2 shfl_xor_f2(float2 v, int m) {
    float2 r;
    r.x = __shfl_xor_sync(0xFFFFFFFFu, v.x, m);
    r.y = __shfl_xor_sync(0xFFFFFFFFu, v.y, m);
    return r;
}

__device__ __forceinline__ void bulk_cp(uint32_t dst, const void* src,
                                        uint32_t bytes, uint32_t mbar) {
    asm volatile(
        "cp.async.bulk.shared::cluster.global.mbarrier::complete_tx::bytes "
        "[%0], [%1], %2, [%3];"
        :: "r"(dst), "l"(src), "r"(bytes), "r"(mbar) : "memory");
}

// CTA: 128x128 output, 128 threads = 4 warps (2x2), warp tile 64x64.
__global__ __launch_bounds__(128, 2)
void dist_bf16_kernel(float* __restrict__ out, int q) {
    __shared__ __align__(128) __nv_bfloat16 sS[BM * D];   // 16 KB
    __shared__ __align__(128) __nv_bfloat16 sT[BN * D];   // 16 KB
    __shared__ float sSn[BM];
    __shared__ float sTn[BN];
    __shared__ __align__(8) uint64_t mbar;

    const int tid  = threadIdx.x;
    const int lane = tid & 31;
    const int warp = tid >> 5;
    const int wm   = warp >> 1;      // 0..1
    const int wn   = warp & 1;       // 0..1
    const int g    = lane >> 2;      // 0..7
    const int i4   = lane & 3;       // 0..3

    const int rowBase = blockIdx.y * BM;
    const int colBase = blockIdx.x * BN;

    const uint32_t mb = (uint32_t)__cvta_generic_to_shared(&mbar);
    const uint32_t sS_base = (uint32_t)__cvta_generic_to_shared(sS);
    const uint32_t sT_base = (uint32_t)__cvta_generic_to_shared(sT);

    if (tid == 0)
        asm volatile("mbarrier.init.shared.b64 [%0], 1;" :: "r"(mb) : "memory");
    __syncthreads();

    if (tid == 0) {
        asm volatile("mbarrier.arrive.expect_tx.shared.b64 _, [%0], %1;"
                     :: "r"(mb), "r"((uint32_t)(BM * D * 2 + BN * D * 2)) : "memory");
        bulk_cp(sS_base, g_s_bf + ((size_t)rowBase << 6), BM * D * 2, mb);
        bulk_cp(sT_base, g_t_bf + ((size_t)colBase << 6), BN * D * 2, mb);
    }

    // Norms staged by regular loads while DMA runs.
    sSn[tid] = g_s_sq[rowBase + tid];
    sTn[tid] = g_t_sq[colBase + tid];

    // Wait for DMA completion (phase 0).
    {
        uint32_t done;
        asm volatile(
            "{\n\t.reg .pred p;\n\t"
            "mbarrier.try_wait.parity.acquire.cta.shared::cta.b64 p, [%1], 0;\n\t"
            "selp.b32 %0, 1, 0, p;\n\t}"
            : "=r"(done) : "r"(mb) : "memory");
        if (!done) {
            asm volatile(
                "{\n\t.reg .pred P1;\n\t"
                "WL_%=:\n\t"
                "mbarrier.try_wait.parity.acquire.cta.shared::cta.b64 P1, [%0], 0, 0x989680;\n\t"
                "@P1 bra.uni WD_%=;\n\tbra.uni WL_%=;\n\tWD_%=:\n\t}"
                :: "r"(mb) : "memory");
        }
    }
    __syncthreads();

    const int mrow = wm * 64;
    const int ncol = wn * 64;
    const int aRow  = mrow + (lane & 15);                 // + mb*16
    const int aXor  = lane & 7;
    const int kAdd  = lane >> 4;                          // chunk +0/+1
    const int bRowL = (lane & 7) + ((lane >> 3) & 1) * 8; // + nk*16 + ncol

    float acc[4][8][4];
#pragma unroll
    for (int a = 0; a < 4; a++)
#pragma unroll
        for (int b = 0; b < 8; b++)
#pragma unroll
            for (int c = 0; c < 4; c++) acc[a][b][c] = 0.f;

#pragma unroll
    for (int ks = 0; ks < 4; ks++) {       // K = 4 * 16
        const int k2 = ks * 2;
        uint32_t a[4][4];
#pragma unroll
        for (int mb2 = 0; mb2 < 4; mb2++) {
            const int row = aRow + mb2 * 16;
            const uint32_t addr =
                sS_base + (uint32_t)(row * 8 + ((k2 + kAdd) ^ aXor)) * 16;
            ldsm_x4(a[mb2][0], a[mb2][1], a[mb2][2], a[mb2][3], addr);
        }
        uint32_t b[4][4];
#pragma unroll
        for (int nk = 0; nk < 4; nk++) {
            const int trow = ncol + nk * 16 + bRowL;
            const uint32_t addr =
                sT_base + (uint32_t)(trow * 8 + ((k2 + kAdd) ^ (trow & 7))) * 16;
            ldsm_x4(b[nk][0], b[nk][1], b[nk][2], b[nk][3], addr);
        }
#pragma unroll
        for (int mb2 = 0; mb2 < 4; mb2++)
#pragma unroll
            for (int nk = 0; nk < 4; nk++) {
                mma_bf16(acc[mb2][nk * 2 + 0], a[mb2], b[nk][0], b[nk][2]);
                mma_bf16(acc[mb2][nk * 2 + 1], a[mb2], b[nk][1], b[nk][3]);
            }
    }

    // ---- Epilogue: quad butterfly per 32-col group -> STG.128 ----
#pragma unroll
    for (int ng = 0; ng < 2; ng++) {
        const int gcol = ncol + ng * 32;
        const float4 tn0 = *reinterpret_cast<const float4*>(&sTn[gcol + 8 * i4]);
        const float4 tn1 = *reinterpret_cast<const float4*>(&sTn[gcol + 8 * i4 + 4]);

#pragma unroll
        for (int mb2 = 0; mb2 < 4; mb2++) {
#pragma unroll
            for (int h = 0; h < 2; h++) {
                float2 pv[4];
#pragma unroll
                for (int k = 0; k < 4; k++)
                    pv[k] = make_float2(acc[mb2][4 * ng + k][2 * h],
                                        acc[mb2][4 * ng + k][2 * h + 1]);

                // stage b=1
                {
                    float2 t0 = shfl_xor_f2(pv[1], 1);
                    float2 t1 = shfl_xor_f2(pv[0], 1);
                    float2 t2 = shfl_xor_f2(pv[3], 1);
                    float2 t3 = shfl_xor_f2(pv[2], 1);
                    if (i4 & 1) { pv[0] = t0; pv[2] = t2; }
                    else        { pv[1] = t1; pv[3] = t3; }
                }
                // stage b=2
                {
                    float2 u0 = shfl_xor_f2(pv[2], 2);
                    float2 u1 = shfl_xor_f2(pv[3], 2);
                    float2 u2 = shfl_xor_f2(pv[0], 2);
                    float2 u3 = shfl_xor_f2(pv[1], 2);
                    if (i4 & 2) { pv[0] = u0; pv[1] = u1; }
                    else        { pv[2] = u2; pv[3] = u3; }
                }

                const int r = mrow + mb2 * 16 + g + 8 * h;
                const float srow = sSn[r];
                float4 o0, o1;
                o0.x = fmaf(-2.f, pv[0].x, srow + tn0.x);
                o0.y = fmaf(-2.f, pv[0].y, srow + tn0.y);
                o0.z = fmaf(-2.f, pv[1].x, srow + tn0.z);
                o0.w = fmaf(-2.f, pv[1].y, srow + tn0.w);
                o1.x = fmaf(-2.f, pv[2].x, srow + tn1.x);
                o1.y = fmaf(-2.f, pv[2].y, srow + tn1.y);
                o1.z = fmaf(-2.f, pv[3].x, srow + tn1.z);
                o1.w = fmaf(-2.f, pv[3].y, srow + tn1.w);

                float* dst = out + (size_t)(rowBase + r) * q + colBase + gcol + 8 * i4;
                *reinterpret_cast<float4*>(dst)     = o0;
                *reinterpret_cast<float4*>(dst + 4) = o1;
            }
        }
    }
}

extern "C" void kernel_launch(void* const* d_in, const int* in_sizes, int n_in,
                              void* d_out, int out_size) {
    const float* s = (const float*)d_in[0];
    const float* t = (const float*)d_in[1];
    float* out = (float*)d_out;

    const int n = in_sizes[0] / D;
    const int q = in_sizes[1] / D;

    dim3 pgrid((((n > q) ? n : q) + 63) / 64, 2);
    prep_kernel<<<pgrid, 256>>>(s, t, n, q);

    dim3 grid(q / BN, n / BM);
    dist_bf16_kernel<<<grid, 128>>>(out, q);
}

// round 10
// speedup vs baseline: 1.0245x; 1.0245x over previous
#include <cuda_runtime.h>
#include <cuda_bf16.h>
#include <cstdint>

// dist[i,j] = ||s_i||^2 + ||t_j||^2 - 2 <s_i, t_j>
// s: [n, 64] fp32, t: [q, 64] fp32, out: [n, q] fp32. n = q = 16384.
// bf16 mma.m16n8k16 + ldmatrix; cp.async.bulk staging of pre-swizzled tiles.
// B rows are fed to ldmatrix through a bit-swapped permutation so the mma
// accumulator layout is ALREADY output-coalesced: lane (g,i4) holds 8
// contiguous output columns of row g. No epilogue shuffles at all.

#define D    64
#define BM   128
#define BN   256
#define MAXNQ 16384

__device__ float g_s_sq[MAXNQ];
__device__ float g_t_sq[MAXNQ];
// Pre-swizzled bf16 tiles: within each 128B row, 16B chunk c stored at c^(row&7).
__device__ __nv_bfloat16 g_s_bf[MAXNQ * D];
__device__ __nv_bfloat16 g_t_bf[MAXNQ * D];

// ---------------- prep: fp32 -> pre-swizzled bf16 + row norms ----------------
__global__ void prep_kernel(const float* __restrict__ s,
                            const float* __restrict__ t, int n, int q) {
    const float* src = blockIdx.y ? t : s;
    __nv_bfloat16* dstb = blockIdx.y ? g_t_bf : g_s_bf;
    float* dstn = blockIdx.y ? g_t_sq : g_s_sq;
    const int lim = blockIdx.y ? q : n;
    const int row = blockIdx.x * 64 + (threadIdx.x >> 2);
    const int part = threadIdx.x & 3;
    if (row >= lim) return;
    const float4* p = reinterpret_cast<const float4*>(src + (size_t)row * D) + part * 4;
    float acc = 0.f;
    uint4* rowq = reinterpret_cast<uint4*>(dstb + (size_t)row * D);
    const int sw = row & 7;
#pragma unroll
    for (int j = 0; j < 2; j++) {
        float4 a = p[2 * j], b = p[2 * j + 1];
        acc += a.x * a.x + a.y * a.y + a.z * a.z + a.w * a.w;
        acc += b.x * b.x + b.y * b.y + b.z * b.z + b.w * b.w;
        __nv_bfloat162 h0 = __float22bfloat162_rn(make_float2(a.x, a.y));
        __nv_bfloat162 h1 = __float22bfloat162_rn(make_float2(a.z, a.w));
        __nv_bfloat162 h2 = __float22bfloat162_rn(make_float2(b.x, b.y));
        __nv_bfloat162 h3 = __float22bfloat162_rn(make_float2(b.z, b.w));
        uint4 u;
        u.x = *reinterpret_cast<uint32_t*>(&h0);
        u.y = *reinterpret_cast<uint32_t*>(&h1);
        u.z = *reinterpret_cast<uint32_t*>(&h2);
        u.w = *reinterpret_cast<uint32_t*>(&h3);
        rowq[(part * 2 + j) ^ sw] = u;   // pre-apply ldmatrix swizzle
    }
    acc += __shfl_xor_sync(0xFFFFFFFF, acc, 1);
    acc += __shfl_xor_sync(0xFFFFFFFF, acc, 2);
    if (part == 0) dstn[row] = acc;
}

// ---------------- helpers ----------------
__device__ __forceinline__ void ldsm_x4(uint32_t& r0, uint32_t& r1,
                                        uint32_t& r2, uint32_t& r3,
                                        uint32_t addr) {
    asm volatile("ldmatrix.sync.aligned.m8n8.x4.shared.b16 {%0,%1,%2,%3}, [%4];"
                 : "=r"(r0), "=r"(r1), "=r"(r2), "=r"(r3) : "r"(addr));
}

__device__ __forceinline__ void mma_bf16(float c[4], const uint32_t a[4],
                                         uint32_t b0, uint32_t b1) {
    asm volatile(
        "mma.sync.aligned.m16n8k16.row.col.f32.bf16.bf16.f32 "
        "{%0,%1,%2,%3}, {%4,%5,%6,%7}, {%8,%9}, {%0,%1,%2,%3};"
        : "+f"(c[0]), "+f"(c[1]), "+f"(c[2]), "+f"(c[3])
        : "r"(a[0]), "r"(a[1]), "r"(a[2]), "r"(a[3]), "r"(b0), "r"(b1));
}

__device__ __forceinline__ void bulk_cp(uint32_t dst, const void* src,
                                        uint32_t bytes, uint32_t mbar) {
    asm volatile(
        "cp.async.bulk.shared::cluster.global.mbarrier::complete_tx::bytes "
        "[%0], [%1], %2, [%3];"
        :: "r"(dst), "l"(src), "r"(bytes), "r"(mbar) : "memory");
}

// CTA: 128x256 output. 256 threads = 8 warps (2x4); warp tile 64x32 per half.
__global__ __launch_bounds__(256, 2)
void dist_bf16_kernel(float* __restrict__ out, int q) {
    __shared__ __align__(128) __nv_bfloat16 sS[BM * D];   // 16 KB
    __shared__ __align__(128) __nv_bfloat16 sT[BN * D];   // 32 KB
    __shared__ float sSn[BM];
    __shared__ float sTn[BN];
    __shared__ __align__(8) uint64_t mbar;

    const int tid  = threadIdx.x;
    const int lane = tid & 31;
    const int warp = tid >> 5;
    const int wm   = warp >> 2;      // 0..1
    const int wn   = warp & 3;       // 0..3
    const int g    = lane >> 2;      // 0..7
    const int i4   = lane & 3;       // 0..3

    const int rowBase = blockIdx.y * BM;
    const int colBase = blockIdx.x * BN;

    const uint32_t mb = (uint32_t)__cvta_generic_to_shared(&mbar);
    const uint32_t sS_base = (uint32_t)__cvta_generic_to_shared(sS);
    const uint32_t sT_base = (uint32_t)__cvta_generic_to_shared(sT);

    if (tid == 0)
        asm volatile("mbarrier.init.shared.b64 [%0], 1;" :: "r"(mb) : "memory");
    __syncthreads();

    if (tid == 0) {
        asm volatile("mbarrier.arrive.expect_tx.shared.b64 _, [%0], %1;"
                     :: "r"(mb), "r"((uint32_t)(BM * D * 2 + BN * D * 2)) : "memory");
        bulk_cp(sS_base, g_s_bf + ((size_t)rowBase << 6), BM * D * 2, mb);
        bulk_cp(sT_base, g_t_bf + ((size_t)colBase << 6), BN * D * 2, mb);
    }

    // Norms staged by regular loads while DMA runs.
    if (tid < BM) sSn[tid] = g_s_sq[rowBase + tid];
    sTn[tid] = g_t_sq[colBase + tid];

    // Wait for DMA completion (phase 0).
    {
        uint32_t done;
        asm volatile(
            "{\n\t.reg .pred p;\n\t"
            "mbarrier.try_wait.parity.acquire.cta.shared::cta.b64 p, [%1], 0;\n\t"
            "selp.b32 %0, 1, 0, p;\n\t}"
            : "=r"(done) : "r"(mb) : "memory");
        if (!done) {
            asm volatile(
                "{\n\t.reg .pred P1;\n\t"
                "WL_%=:\n\t"
                "mbarrier.try_wait.parity.acquire.cta.shared::cta.b64 P1, [%0], 0, 0x989680;\n\t"
                "@P1 bra.uni WD_%=;\n\tbra.uni WL_%=;\n\tWD_%=:\n\t}"
                :: "r"(mb) : "memory");
        }
    }
    __syncthreads();

    const int mrow = wm * 64;
    // A-fragment lane addressing (unchanged):
    const int aRow  = mrow + (lane & 15);                 // + mb*16
    const int aXor  = lane & 7;
    const int kAddA = lane >> 4;                          // chunk +0/+1

    // B-fragment PERMUTED lane addressing:
    // matrix m = lane>>3: (nfB = m&1) selects n8 block in the nk pair,
    // (kAddB = m>>1) selects k chunk. Row j = lane&7 within the matrix feeds
    // mma n8-index j = [j2 j1 j0]; we want t physical row
    // p = 16*j2 + 8*j1 + 2*nf + j0 at that slot (bit-swap permutation).
    const int mSel  = lane >> 3;
    const int nfB   = mSel & 1;
    const int kAddB = mSel >> 1;
    const int j     = lane & 7;
    const int pBase = ((j & 4) << 2) + ((j & 2) << 2) + (j & 1) + 2 * nfB;
    // trow = ncol + pBase + 4*nk

#pragma unroll 1
    for (int nb = 0; nb < 2; nb++) {
        const int ncol = nb * 128 + wn * 32;

        float acc[4][4][4];
#pragma unroll
        for (int a = 0; a < 4; a++)
#pragma unroll
            for (int b = 0; b < 4; b++)
#pragma unroll
                for (int c = 0; c < 4; c++) acc[a][b][c] = 0.f;

#pragma unroll
        for (int ks = 0; ks < 4; ks++) {       // K = 4 * 16
            const int k2 = ks * 2;
            uint32_t a[4][4];
#pragma unroll
            for (int mb2 = 0; mb2 < 4; mb2++) {
                const int row = aRow + mb2 * 16;
                const uint32_t addr =
                    sS_base + (uint32_t)(row * 8 + ((k2 + kAddA) ^ aXor)) * 16;
                ldsm_x4(a[mb2][0], a[mb2][1], a[mb2][2], a[mb2][3], addr);
            }
            uint32_t b[2][4];
#pragma unroll
            for (int nk = 0; nk < 2; nk++) {
                const int trow = ncol + pBase + 4 * nk;
                const uint32_t addr =
                    sT_base + (uint32_t)(trow * 8 + ((k2 + kAddB) ^ (trow & 7))) * 16;
                ldsm_x4(b[nk][0], b[nk][1], b[nk][2], b[nk][3], addr);
            }
#pragma unroll
            for (int mb2 = 0; mb2 < 4; mb2++)
#pragma unroll
                for (int nk = 0; nk < 2; nk++) {
                    mma_bf16(acc[mb2][nk * 2 + 0], a[mb2], b[nk][0], b[nk][2]);
                    mma_bf16(acc[mb2][nk * 2 + 1], a[mb2], b[nk][1], b[nk][3]);
                }
        }

        // ---- Epilogue: accs are already coalesced; straight STG.128 ----
        // acc[mb2][nf][2h+c] = cross for row (mrow+mb2*16+g+8h),
        // physical col ncol + 8*i4 + 2*nf + c.
        const float4 tn0 = *reinterpret_cast<const float4*>(&sTn[ncol + 8 * i4]);
        const float4 tn1 = *reinterpret_cast<const float4*>(&sTn[ncol + 8 * i4 + 4]);

#pragma unroll
        for (int mb2 = 0; mb2 < 4; mb2++) {
#pragma unroll
            for (int h = 0; h < 2; h++) {
                const int r = mrow + mb2 * 16 + g + 8 * h;
                const float srow = sSn[r];
                float4 o0, o1;
                o0.x = fmaf(-2.f, acc[mb2][0][2 * h + 0], srow + tn0.x);
                o0.y = fmaf(-2.f, acc[mb2][0][2 * h + 1], srow + tn0.y);
                o0.z = fmaf(-2.f, acc[mb2][1][2 * h + 0], srow + tn0.z);
                o0.w = fmaf(-2.f, acc[mb2][1][2 * h + 1], srow + tn0.w);
                o1.x = fmaf(-2.f, acc[mb2][2][2 * h + 0], srow + tn1.x);
                o1.y = fmaf(-2.f, acc[mb2][2][2 * h + 1], srow + tn1.y);
                o1.z = fmaf(-2.f, acc[mb2][3][2 * h + 0], srow + tn1.z);
                o1.w = fmaf(-2.f, acc[mb2][3][2 * h + 1], srow + tn1.w);

                float* dst = out + (size_t)(rowBase + r) * q + colBase + ncol + 8 * i4;
                *reinterpret_cast<float4*>(dst)     = o0;
                *reinterpret_cast<float4*>(dst + 4) = o1;
            }
        }
    }
}

extern "C" void kernel_launch(void* const* d_in, const int* in_sizes, int n_in,
                              void* d_out, int out_size) {
    const float* s = (const float*)d_in[0];
    const float* t = (const float*)d_in[1];
    float* out = (float*)d_out;

    const int n = in_sizes[0] / D;
    const int q = in_sizes[1] / D;

    dim3 pgrid((((n > q) ? n : q) + 63) / 64, 2);
    prep_kernel<<<pgrid, 256>>>(s, t, n, q);

    dim3 grid(q / BN, n / BM);
    dist_bf16_kernel<<<grid, 256>>>(out, q);
}

// round 12
// speedup vs baseline: 1.3214x; 1.2898x over previous
#include <cuda_runtime.h>
#include <cuda_bf16.h>
#include <cstdint>

// dist[i,j] = ||s_i||^2 + ||t_j||^2 - 2 <s_i, t_j>
// s: [n, 64] fp32, t: [q, 64] fp32, out: [n, q] fp32. n = q = 16384.
// bf16 mma.m16n8k16 + ldmatrix; cp.async.bulk staging of pre-swizzled tiles.
// t rows are stored PERMUTED in gmem (bit-swap within 32-row blocks) so that
// conflict-free consecutive-row B ldmatrix yields an accumulator layout that
// is already output-coalesced: lane (g,i4) holds 8 contiguous output columns
// of row g. No epilogue shuffles; straight STG.128.

#define D    64
#define BM   128
#define BN   256
#define MAXNQ 16384

__device__ float g_s_sq[MAXNQ];
__device__ float g_t_sq[MAXNQ];
// Pre-swizzled bf16 tiles: within each 128B row, 16B chunk c stored at c^(row&7).
__device__ __nv_bfloat16 g_s_bf[MAXNQ * D];
__device__ __nv_bfloat16 g_t_bf[MAXNQ * D];   // rows permuted within 32-blocks

// Involutive bit-swap within a 32-row block: fields (b4,b3) <-> (b2,b1).
// Storage slot for physical row offset p; also maps n-index -> physical col.
__host__ __device__ __forceinline__ int perm32(int p) {
    return (((p >> 2) & 1) << 4) | (((p >> 1) & 1) << 3) |
           (((p >> 4) & 1) << 2) | (((p >> 3) & 1) << 1) | (p & 1);
}

// ---------------- prep: fp32 -> pre-swizzled bf16 + row norms ----------------
__global__ void prep_kernel(const float* __restrict__ s,
                            const float* __restrict__ t, int n, int q) {
    const float* src = blockIdx.y ? t : s;
    __nv_bfloat16* dstb = blockIdx.y ? g_t_bf : g_s_bf;
    float* dstn = blockIdx.y ? g_t_sq : g_s_sq;
    const int lim = blockIdx.y ? q : n;
    const int row = blockIdx.x * 64 + (threadIdx.x >> 2);
    const int part = threadIdx.x & 3;
    if (row >= lim) return;
    // t rows: permute storage slot within each 32-row block.
    const int drow = blockIdx.y ? ((row & ~31) | perm32(row & 31)) : row;
    const float4* p = reinterpret_cast<const float4*>(src + (size_t)row * D) + part * 4;
    float acc = 0.f;
    uint4* rowq = reinterpret_cast<uint4*>(dstb + (size_t)drow * D);
    const int sw = drow & 7;
#pragma unroll
    for (int j = 0; j < 2; j++) {
        float4 a = p[2 * j], b = p[2 * j + 1];
        acc += a.x * a.x + a.y * a.y + a.z * a.z + a.w * a.w;
        acc += b.x * b.x + b.y * b.y + b.z * b.z + b.w * b.w;
        __nv_bfloat162 h0 = __float22bfloat162_rn(make_float2(a.x, a.y));
        __nv_bfloat162 h1 = __float22bfloat162_rn(make_float2(a.z, a.w));
        __nv_bfloat162 h2 = __float22bfloat162_rn(make_float2(b.x, b.y));
        __nv_bfloat162 h3 = __float22bfloat162_rn(make_float2(b.z, b.w));
        uint4 u;
        u.x = *reinterpret_cast<uint32_t*>(&h0);
        u.y = *reinterpret_cast<uint32_t*>(&h1);
        u.z = *reinterpret_cast<uint32_t*>(&h2);
        u.w = *reinterpret_cast<uint32_t*>(&h3);
        rowq[(part * 2 + j) ^ sw] = u;   // pre-apply ldmatrix swizzle
    }
    acc += __shfl_xor_sync(0xFFFFFFFF, acc, 1);
    acc += __shfl_xor_sync(0xFFFFFFFF, acc, 2);
    if (part == 0) dstn[row] = acc;      // norms stay in PHYSICAL order
}

// ---------------- helpers ----------------
__device__ __forceinline__ void ldsm_x4(uint32_t& r0, uint32_t& r1,
                                        uint32_t& r2, uint32_t& r3,
                                        uint32_t addr) {
    asm volatile("ldmatrix.sync.aligned.m8n8.x4.shared.b16 {%0,%1,%2,%3}, [%4];"
                 : "=r"(r0), "=r"(r1), "=r"(r2), "=r"(r3) : "r"(addr));
}

__device__ __forceinline__ void mma_bf16(float c[4], const uint32_t a[4],
                                         uint32_t b0, uint32_t b1) {
    asm volatile(
        "mma.sync.aligned.m16n8k16.row.col.f32.bf16.bf16.f32 "
        "{%0,%1,%2,%3}, {%4,%5,%6,%7}, {%8,%9}, {%0,%1,%2,%3};"
        : "+f"(c[0]), "+f"(c[1]), "+f"(c[2]), "+f"(c[3])
        : "r"(a[0]), "r"(a[1]), "r"(a[2]), "r"(a[3]), "r"(b0), "r"(b1));
}

__device__ __forceinline__ void bulk_cp(uint32_t dst, const void* src,
                                        uint32_t bytes, uint32_t mbar) {
    asm volatile(
        "cp.async.bulk.shared::cluster.global.mbarrier::complete_tx::bytes "
        "[%0], [%1], %2, [%3];"
        :: "r"(dst), "l"(src), "r"(bytes), "r"(mbar) : "memory");
}

// CTA: 128x256 output. 256 threads = 8 warps (2x4); warp tile 64x32 per half.
__global__ __launch_bounds__(256, 2)
void dist_bf16_kernel(float* __restrict__ out, int q) {
    __shared__ __align__(128) __nv_bfloat16 sS[BM * D];   // 16 KB
    __shared__ __align__(128) __nv_bfloat16 sT[BN * D];   // 32 KB
    __shared__ float sSn[BM];
    __shared__ float sTn[BN];
    __shared__ __align__(8) uint64_t mbar;

    const int tid  = threadIdx.x;
    const int lane = tid & 31;
    const int warp = tid >> 5;
    const int wm   = warp >> 2;      // 0..1
    const int wn   = warp & 3;       // 0..3
    const int g    = lane >> 2;      // 0..7
    const int i4   = lane & 3;       // 0..3

    const int rowBase = blockIdx.y * BM;
    const int colBase = blockIdx.x * BN;

    const uint32_t mb = (uint32_t)__cvta_generic_to_shared(&mbar);
    const uint32_t sS_base = (uint32_t)__cvta_generic_to_shared(sS);
    const uint32_t sT_base = (uint32_t)__cvta_generic_to_shared(sT);

    if (tid == 0)
        asm volatile("mbarrier.init.shared.b64 [%0], 1;" :: "r"(mb) : "memory");
    __syncthreads();

    if (tid == 0) {
        asm volatile("mbarrier.arrive.expect_tx.shared.b64 _, [%0], %1;"
                     :: "r"(mb), "r"((uint32_t)(BM * D * 2 + BN * D * 2)) : "memory");
        bulk_cp(sS_base, g_s_bf + ((size_t)rowBase << 6), BM * D * 2, mb);
        bulk_cp(sT_base, g_t_bf + ((size_t)colBase << 6), BN * D * 2, mb);
    }

    // Norms staged by regular loads while DMA runs.
    if (tid < BM) sSn[tid] = g_s_sq[rowBase + tid];
    sTn[tid] = g_t_sq[colBase + tid];

    // Wait for DMA completion (phase 0).
    {
        uint32_t done;
        asm volatile(
            "{\n\t.reg .pred p;\n\t"
            "mbarrier.try_wait.parity.acquire.cta.shared::cta.b64 p, [%1], 0;\n\t"
            "selp.b32 %0, 1, 0, p;\n\t}"
            : "=r"(done) : "r"(mb) : "memory");
        if (!done) {
            asm volatile(
                "{\n\t.reg .pred P1;\n\t"
                "WL_%=:\n\t"
                "mbarrier.try_wait.parity.acquire.cta.shared::cta.b64 P1, [%0], 0, 0x989680;\n\t"
                "@P1 bra.uni WD_%=;\n\tbra.uni WL_%=;\n\tWD_%=:\n\t}"
                :: "r"(mb) : "memory");
        }
    }
    __syncthreads();

    const int mrow = wm * 64;
    const int aRow  = mrow + (lane & 15);                 // + mb*16
    const int aXor  = lane & 7;
    const int kAdd  = lane >> 4;                          // chunk +0/+1
    const int bRowL = (lane & 7) + ((lane >> 3) & 1) * 8; // + nk*16 + ncol

#pragma unroll 1
    for (int nb = 0; nb < 2; nb++) {
        const int ncol = nb * 128 + wn * 32;

        float acc[4][4][4];
#pragma unroll
        for (int a = 0; a < 4; a++)
#pragma unroll
            for (int b = 0; b < 4; b++)
#pragma unroll
                for (int c = 0; c < 4; c++) acc[a][b][c] = 0.f;

#pragma unroll
        for (int ks = 0; ks < 4; ks++) {       // K = 4 * 16
            const int k2 = ks * 2;
            uint32_t a[4][4];
#pragma unroll
            for (int mb2 = 0; mb2 < 4; mb2++) {
                const int row = aRow + mb2 * 16;
                const uint32_t addr =
                    sS_base + (uint32_t)(row * 8 + ((k2 + kAdd) ^ aXor)) * 16;
                ldsm_x4(a[mb2][0], a[mb2][1], a[mb2][2], a[mb2][3], addr);
            }
            uint32_t b[2][4];
#pragma unroll
            for (int nk = 0; nk < 2; nk++) {
                const int trow = ncol + nk * 16 + bRowL;   // consecutive rows
                const uint32_t addr =
                    sT_base + (uint32_t)(trow * 8 + ((k2 + kAdd) ^ (trow & 7))) * 16;
                ldsm_x4(b[nk][0], b[nk][1], b[nk][2], b[nk][3], addr);
            }
#pragma unroll
            for (int mb2 = 0; mb2 < 4; mb2++)
#pragma unroll
                for (int nk = 0; nk < 2; nk++) {
                    mma_bf16(acc[mb2][nk * 2 + 0], a[mb2], b[nk][0], b[nk][2]);
                    mma_bf16(acc[mb2][nk * 2 + 1], a[mb2], b[nk][1], b[nk][3]);
                }
        }

        // ---- Epilogue: accs already coalesced (storage permutation) ----
        // acc[mb2][nf][2h+c] = cross for row (mrow+mb2*16+g+8h),
        // PHYSICAL col ncol + 8*i4 + 2*nf + c.
        const float4 tn0 = *reinterpret_cast<const float4*>(&sTn[ncol + 8 * i4]);
        const float4 tn1 = *reinterpret_cast<const float4*>(&sTn[ncol + 8 * i4 + 4]);

#pragma unroll
        for (int mb2 = 0; mb2 < 4; mb2++) {
#pragma unroll
            for (int h = 0; h < 2; h++) {
                const int r = mrow + mb2 * 16 + g + 8 * h;
                const float srow = sSn[r];
                float4 o0, o1;
                o0.x = fmaf(-2.f, acc[mb2][0][2 * h + 0], srow + tn0.x);
                o0.y = fmaf(-2.f, acc[mb2][0][2 * h + 1], srow + tn0.y);
                o0.z = fmaf(-2.f, acc[mb2][1][2 * h + 0], srow + tn0.z);
                o0.w = fmaf(-2.f, acc[mb2][1][2 * h + 1], srow + tn0.w);
                o1.x = fmaf(-2.f, acc[mb2][2][2 * h + 0], srow + tn1.x);
                o1.y = fmaf(-2.f, acc[mb2][2][2 * h + 1], srow + tn1.y);
                o1.z = fmaf(-2.f, acc[mb2][3][2 * h + 0], srow + tn1.z);
                o1.w = fmaf(-2.f, acc[mb2][3][2 * h + 1], srow + tn1.w);

                float* dst = out + (size_t)(rowBase + r) * q + colBase + ncol + 8 * i4;
                *reinterpret_cast<float4*>(dst)     = o0;
                *reinterpret_cast<float4*>(dst + 4) = o1;
            }
        }
    }
}

extern "C" void kernel_launch(void* const* d_in, const int* in_sizes, int n_in,
                              void* d_out, int out_size) {
    const float* s = (const float*)d_in[0];
    const float* t = (const float*)d_in[1];
    float* out = (float*)d_out;

    const int n = in_sizes[0] / D;
    const int q = in_sizes[1] / D;

    dim3 pgrid((((n > q) ? n : q) + 63) / 64, 2);
    prep_kernel<<<pgrid, 256>>>(s, t, n, q);

    dim3 grid(q / BN, n / BM);
    dist_bf16_kernel<<<grid, 256>>>(out, q);
}